// round 15
// baseline (speedup 1.0000x reference)
#include <cuda_runtime.h>

#define NB 128
#define NT 1024
#define ND 3
#define NH 512
#define NC 3
#define NSLICE 16      // h-slices per batch group = CTAs per group
#define HS 32          // h per slice
#define NGRP 16        // batch groups (8 rows); each CTA serves 2 groups
#define BGr 8          // batch rows per group
#define THREADS 512
#define RSTRIDE 516    // rW row stride in words (pad -> conflict-free A loads)
#define PSTRIDE 40     // psum row stride: offsets {0,8,16,24}+h -> conflict-free
#define RWBUF   (16 * RSTRIDE)          // words per rW buffer
#define PSUMW   (4 * 2 * 16 * PSTRIDE)  // words per psum buffer

typedef unsigned int u32;

// chunk-granular dataflow flags: [group][slice][row][chunk(h8)][t], t fastest.
// Each (slice,row,chunk) stream is 4KB apart -> pollers decontended.
// Zero-initialized; each slot flips parity exactly once per launch; slot
// [g][s][0][0][NT-1] is rewritten only by CTA (g,s) itself at launch end,
// so the pre-loop parity probe is race-free.
__device__ int g_flag[NGRP][NSLICE][BGr][4][NT];

static __device__ __forceinline__ int ld_acq(const int* p) {
    int v;
    asm volatile("ld.acquire.gpu.global.s32 %0, [%1];" : "=r"(v) : "l"(p) : "memory");
    return v;
}
static __device__ __forceinline__ void wait_flag(const int* pf, int stale) {
    while (ld_acq(pf) == stale) {}
}
// poll 4 flags concurrently (4 loads in flight; one RT when all ready)
static __device__ __forceinline__ void wait4(const int* p0, const int* p1,
                                             const int* p2, const int* p3,
                                             int stale) {
    int v0, v1, v2, v3;
    do {
        v0 = ld_acq(p0); v1 = ld_acq(p1); v2 = ld_acq(p2); v3 = ld_acq(p3);
    } while (v0 == stale || v1 == stale || v2 == stale || v3 == stale);
}
static __device__ __forceinline__ u32 to_tf32(float f) {
    u32 o; asm("cvt.rna.tf32.f32 %0, %1;" : "=r"(o) : "f"(f)); return o;
}
static __device__ __forceinline__ void mma_tf32(
    float& c0, float& c1, float& c2, float& c3,
    u32 a0, u32 a1, u32 a2, u32 a3, u32 b0, u32 b1)
{
    asm volatile(
        "mma.sync.aligned.m16n8k8.row.col.f32.tf32.tf32.f32 "
        "{%0,%1,%2,%3}, {%4,%5,%6,%7}, {%8,%9}, {%0,%1,%2,%3};"
        : "+f"(c0), "+f"(c1), "+f"(c2), "+f"(c3)
        : "r"(a0), "r"(a1), "r"(a2), "r"(a3), "r"(b0), "r"(b1));
}

extern __shared__ float smem_f[];

// Grid 128 = 8 pairs x 16 slices, 1 CTA/SM. Skewed single-pass scheme:
// mma rows 0-7 = group gA step t, rows 8-15 = group gB step t-1.
// Warp w = hq*4+kq.
//   stage role:  tile rows hq*4..+4 of k-strip kq (raw fp32; tf32 HMMA reads
//                top bits); per-lane wait4 on exactly the 4 producer flags
//                covering its copied words. Sync: named bar 1+kq (kq-quad).
//   mma role:    16 k8-blocks into double-buffered psum. Sync: bar 5+hq.
//   reduce role: tile rows kq*4..+4 x h-chunk hq (8 h); lane=(row*8+h);
//                publishes per-(row,chunk) flags right after its own STGs.
// No __syncthreads in the loop: the four hq-quads / kq-quads pipeline
// independently and publish early.
__global__ void __launch_bounds__(THREADS, 1)
flipflop_main(const float* __restrict__ inputs,
              const float* __restrict__ Wv,
              const float* __restrict__ Pv,
              const float* __restrict__ bv,
              const float* __restrict__ Wz,
              const float* __restrict__ Pz,
              const float* __restrict__ bz,
              const float* __restrict__ fcW,
              const float* __restrict__ fcb,
              float* __restrict__ out,
              float* __restrict__ hidden)
{
    u32*   rW = (u32*)smem_f;                 // 2 x [16][RSTRIDE] fp32 bits, 66 KB
    float* ps = smem_f + 2 * RWBUF;           // 2 x [4kq][2][16rows][PSTRIDE], 41 KB

    const int tid   = threadIdx.x;
    const int pair  = blockIdx.x >> 4;
    const int slice = blockIdx.x & 15;
    const int gA    = pair * 2, gB = gA + 1;
    const int gbA   = gA * BGr, gbB = gB * BGr;
    const int w     = tid >> 5;
    const int lane  = tid & 31;
    const int hq    = w >> 2;
    const int kq    = w & 3;
    const int g     = lane >> 2;
    const int t4    = lane & 3;

    // ---- B fragments (weights) in registers, tf32 RNA, 64 regs ----
    u32 bz0[16], bz1[16], bv0[16], bv1[16];
    {
        const int hB = slice * HS + hq * 8 + g;
        const float* zrow = Wz + (size_t)hB * NH + kq * 128 + t4;
        const float* vrow = Wv + (size_t)hB * NH + kq * 128 + t4;
        #pragma unroll
        for (int kb = 0; kb < 16; ++kb) {
            bz0[kb] = to_tf32(zrow[kb*8]);
            bz1[kb] = to_tf32(zrow[kb*8 + 4]);
            bv0[kb] = to_tf32(vrow[kb*8]);
            bv1[kb] = to_tf32(vrow[kb*8 + 4]);
        }
    }

    // parity probes (own slots; rewritten only by this CTA near launch end)
    int parA, parB;
    asm volatile("ld.relaxed.gpu.global.s32 %0, [%1];"
                 : "=r"(parA) : "l"(&g_flag[gA][slice][0][0][NT-1]));
    asm volatile("ld.relaxed.gpu.global.s32 %0, [%1];"
                 : "=r"(parB) : "l"(&g_flag[gB][slice][0][0][NT-1]));
    const int readyA = parA ^ 1, readyB = parB ^ 1;

    // ---- reduce-role constants: warp (hq,kq) owns tile rows kq*4..+4,
    //      h-chunk hq; lane = row_local*8 + h_local ----
    const int  rl_row   = lane >> 3;              // 0..3
    const int  rl_h     = lane & 7;               // 0..7
    const int  tile_row = kq * 4 + rl_row;        // 0..15
    const bool redA     = (kq < 2);               // tile rows 0-7 = group A
    const int  rrowg    = redA ? (gbA + tile_row) : (gbB + (tile_row - 8));
    const int  hg       = slice * HS + hq * 8 + rl_h;
    const float pz0 = Pz[hg*3+0], pz1 = Pz[hg*3+1], pz2 = Pz[hg*3+2];
    float pm0 = 0.f, pm1 = 0.f, pm2 = 0.f;        // P_m: bottom half zeroed
    if (hg < NH/2) { pm0 = Pv[hg*3+0]; pm1 = Pv[hg*3+1]; pm2 = Pv[hg*3+2]; }
    const float bzr = bz[hg];
    const float bvr = bv[hg];
    const float* xrow = inputs + (size_t)rrowg * NT * ND;
    float*       hout = hidden + ((size_t)rrowg * NT) * NH + hg;
    int* myflag = redA ? &g_flag[gA][slice][tile_row & 7][hq][0]
                       : &g_flag[gB][slice][tile_row & 7][hq][0];
    const int myready = redA ? readyA : readyB;

    // ---- stage-role: warp stages tile rows [hq*4, hq*4+4) of k-strip kq ----
    const bool stA    = (hq < 2);                 // tile rows 0-7 <- group A
    const int  srow   = hq * 4 + (lane >> 3);     // tile row 0..15
    const int  sch    = (lane & 7) * 4;           // word chunk within window
    const int  sgrow  = stA ? (gbA + (srow & 7)) : (gbB + (srow & 7));
    const float* sg   = hidden + ((size_t)sgrow * NT) * NH + kq * 128 + sch;
    u32*       sd0    = rW + srow * RSTRIDE + kq * 128 + sch;
    // this lane's copied words hit producer slices kq*4+j (j=0..3), all in
    // h-chunk (lane&7)>>1 of row (srow&7):
    const int  schunk = (lane & 7) >> 1;
    const int  pgrp   = stA ? gA : gB;
    const int  ppar   = stA ? parA : parB;
    const int* pf0 = &g_flag[pgrp][kq*4 + 0][srow & 7][schunk][0];
    const int* pf1 = &g_flag[pgrp][kq*4 + 1][srow & 7][schunk][0];
    const int* pf2 = &g_flag[pgrp][kq*4 + 2][srow & 7][schunk][0];
    const int* pf3 = &g_flag[pgrp][kq*4 + 3][srow & 7][schunk][0];

    // ---- A-frag / psum indices ----
    const int ab0 = g * RSTRIDE + t4;
    const int ab1 = (g + 8) * RSTRIDE + t4;
    const int koff0 = kq * 128;
    const int psz_i = ((kq * 2 + 0) * 16 + g) * PSTRIDE + hq * 8 + t4 * 2;
    const int psv_i = ((kq * 2 + 1) * 16 + g) * PSTRIDE + hq * 8 + t4 * 2;

    // zero both rW buffers -> r0 = 0 for both groups, both parities
    for (int i = tid; i < 2 * RWBUF; i += THREADS) rW[i] = 0u;
    __syncthreads();

    float r_prev = 0.f;          // this lane's r at its (row, h)

    for (int t = 0; t <= NT; ++t) {
        const int xs = redA ? t : (t - 1);        // step this warp emits
        float x0 = 0.f, x1 = 0.f, x2 = 0.f;
        if (xs >= 0 && xs < NT) {
            x0 = xrow[xs*3+0]; x1 = xrow[xs*3+1]; x2 = xrow[xs*3+2];
        }

        // ---- poll + stage (raw fp32; tf32 HMMA ignores low mantissa) ----
        const bool do_stage = stA ? (t >= 1 && t < NT) : (t >= 2);
        const int  tsrc     = stA ? (t - 1) : (t - 2);
        if (do_stage) {
            wait4(pf0 + tsrc, pf1 + tsrc, pf2 + tsrc, pf3 + tsrc, ppar);
            const float* s = sg + (size_t)tsrc * NH;
            u32* sd = sd0 + (t & 1) * RWBUF;
            #pragma unroll
            for (int j = 0; j < 4; ++j)               // windows of 32 k
                *(uint4*)(sd + j * 32) = *(const uint4*)(s + j * 32);
        }
        asm volatile("bar.sync %0, 128;" :: "r"(1 + kq) : "memory");

        // ---- mma pass: rows 0-7 = A(t), rows 8-15 = B(t-1) ----
        float* pb = ps + (t & 1) * PSUMW;
        if (t >= 1) {
            const u32* rWb = rW + (t & 1) * RWBUF;
            float cz0=0.f,cz1=0.f,cz2=0.f,cz3=0.f, cv0=0.f,cv1=0.f,cv2=0.f,cv3=0.f;
            #pragma unroll
            for (int kb = 0; kb < 16; ++kb) {
                const int ko = koff0 + kb * 8;
                u32 a0 = rWb[ab0 + ko], a1 = rWb[ab1 + ko];
                u32 a2 = rWb[ab0 + ko + 4], a3 = rWb[ab1 + ko + 4];
                mma_tf32(cz0,cz1,cz2,cz3, a0,a1,a2,a3, bz0[kb],bz1[kb]);
                mma_tf32(cv0,cv1,cv2,cv3, a0,a1,a2,a3, bv0[kb],bv1[kb]);
            }
            *(float2*)(pb + psz_i)               = make_float2(cz0, cz1);
            *(float2*)(pb + psz_i + 8 * PSTRIDE) = make_float2(cz2, cz3);
            *(float2*)(pb + psv_i)               = make_float2(cv0, cv1);
            *(float2*)(pb + psv_i + 8 * PSTRIDE) = make_float2(cv2, cv3);
        }
        asm volatile("bar.sync %0, 128;" :: "r"(5 + hq) : "memory");

        // ---- reduce + gates + per-(row,chunk) publish ----
        {
            const bool run  = (xs >= 0) && (xs < NT);
            const bool hasp = redA ? (t >= 1) : (t >= 2);
            if (run) {
                float sz = 0.f, sv = 0.f;
                if (hasp) {
                    #pragma unroll
                    for (int q = 0; q < 4; ++q) {
                        sz += pb[((q*2 + 0) * 16 + tile_row) * PSTRIDE + hq*8 + rl_h];
                        sv += pb[((q*2 + 1) * 16 + tile_row) * PSTRIDE + hq*8 + rl_h];
                    }
                }
                const float az = sz + x0*pz0 + x1*pz1 + x2*pz2 + bzr;
                const float av = sv + x0*pm0 + x1*pm1 + x2*pm2 + bvr;
                const float z  = 1.f / (1.f + __expf(-az));
                const float c  = 1.f / (1.f + __expf(-av));
                const float rn = fmaf(z, c - r_prev, r_prev);
                r_prev = rn;
                hout[(size_t)xs * NH] = rn;
                __syncwarp();                     // order the 8 h-STGs of each row
                if (rl_h == 0)
                    asm volatile("st.release.gpu.global.s32 [%0], %1;"
                                 :: "l"(myflag + xs), "r"(myready) : "memory");
            }
        }
    }

    // before fc: wait for final flags of all (slice=w, row, chunk) streams
    wait_flag(&g_flag[gA][w][lane & 7][(lane >> 3) & 3][NT-1], parA);
    wait_flag(&g_flag[gB][w][lane & 7][(lane >> 3) & 3][NT-1], parB);
    __syncthreads();

    // ================= fc epilogue =================
    float* fw = smem_f;                           // reuse smem
    for (int i = tid; i < NC * NH; i += THREADS) fw[i] = fcW[i];
    const float fb0 = fcb[0], fb1 = fcb[1], fb2 = fcb[2];
    __syncthreads();

    const int hh = lane;
    float4 fw0[4], fw1[4], fw2[4];
    #pragma unroll
    for (int j = 0; j < 4; ++j) {
        const int i = hh + j * 32;
        fw0[j] = ((const float4*)(fw + 0 * NH))[i];
        fw1[j] = ((const float4*)(fw + 1 * NH))[i];
        fw2[j] = ((const float4*)(fw + 2 * NH))[i];
    }

    const int row = (w < 8) ? (gbA + (w & 7)) : (gbB + (w & 7));
    const int t0  = slice * (NT / NSLICE);
    const float* hp = hidden + ((size_t)row * NT + t0) * NH;
    float*       op = out    + ((size_t)row * NT + t0) * NC;

    for (int it = 0; it < NT / NSLICE; ++it) {
        const float4* h4 = (const float4*)(hp + (size_t)it * NH);
        float a0 = 0.f, a1 = 0.f, a2 = 0.f;
        #pragma unroll
        for (int j = 0; j < 4; ++j) {
            float4 h = h4[hh + j * 32];
            a0 += h.x*fw0[j].x + h.y*fw0[j].y + h.z*fw0[j].z + h.w*fw0[j].w;
            a1 += h.x*fw1[j].x + h.y*fw1[j].y + h.z*fw1[j].z + h.w*fw1[j].w;
            a2 += h.x*fw2[j].x + h.y*fw2[j].y + h.z*fw2[j].z + h.w*fw2[j].w;
        }
        #pragma unroll
        for (int o = 16; o; o >>= 1) {
            a0 += __shfl_down_sync(0xffffffffu, a0, o);
            a1 += __shfl_down_sync(0xffffffffu, a1, o);
            a2 += __shfl_down_sync(0xffffffffu, a2, o);
        }
        if (hh == 0) {
            op[it*3+0] = a0 + fb0;
            op[it*3+1] = a1 + fb1;
            op[it*3+2] = a2 + fb2;
        }
    }
}

extern "C" void kernel_launch(void* const* d_in, const int* in_sizes, int n_in,
                              void* d_out, int out_size)
{
    const float* inputs = (const float*)d_in[0];
    const float* Wv     = (const float*)d_in[1];
    const float* Pv     = (const float*)d_in[2];
    const float* b_v    = (const float*)d_in[3];
    const float* Wz     = (const float*)d_in[4];
    const float* Pz     = (const float*)d_in[5];
    const float* b_z    = (const float*)d_in[6];
    const float* fcW    = (const float*)d_in[7];
    const float* fcb    = (const float*)d_in[8];

    // outputs concatenated in reference return order: out (B,T,C) then hidden (B,T,H)
    float* out    = (float*)d_out;
    float* hidden = out + (size_t)NB * NT * NC;

    const int smem_bytes = (2 * RWBUF + 2 * PSUMW) * 4;
    cudaFuncSetAttribute(flipflop_main,
                         cudaFuncAttributeMaxDynamicSharedMemorySize, smem_bytes);

    flipflop_main<<<(NGRP / 2) * NSLICE, THREADS, smem_bytes>>>(
        inputs, Wv, Pv, b_v, Wz, Pz, b_z, fcW, fcb, out, hidden);
}

// round 16
// speedup vs baseline: 1.1709x; 1.1709x over previous
#include <cuda_runtime.h>
#include <cuda_fp16.h>

#define NB 128
#define NT 1024
#define ND 3
#define NH 512
#define NC 3
#define NSLICE 16      // h-slices per batch group = CTAs per group
#define HS 32          // h per slice
#define NGRP 16        // batch groups (8 rows); each CTA serves 2 groups
#define BGr 8          // batch rows per group
#define THREADS 512
#define RSTRIDE 260    // rW row stride in 32b words (512 f16 = 256 w + 4 pad;
                       // 260 mod 32 = 4 -> A-frag LDS conflict-free)
#define PSTRIDE 34     // psum row stride in words
#define PSUMW (4 * 2 * 16 * PSTRIDE)   // words per psum buffer

typedef unsigned int u32;

// per-(group, slice, row, t) dataflow flags. Row-level granularity:
// each reduce warp publishes its own row; each consumer lane polls exactly
// the (slice,row) it stages -> parallel single-RT detection, no bulk sync.
// Zero-initialized; every slot flips parity exactly once per launch.
__device__ int g_flag[NGRP][NSLICE][BGr][NT];

static __device__ __forceinline__ void wait_flag(const int* pf, int stale) {
    int v;
    do {
        asm volatile("ld.acquire.gpu.global.s32 %0, [%1];"
                     : "=r"(v) : "l"(pf) : "memory");
    } while (v == stale);
}
static __device__ __forceinline__ u32 pack_h2(float lo, float hi) {
    __half2 h = __floats2half2_rn(lo, hi);
    return *(u32*)&h;
}
static __device__ __forceinline__ void mma_f16(
    float& c0, float& c1, float& c2, float& c3,
    u32 a0, u32 a1, u32 a2, u32 a3, u32 b0, u32 b1)
{
    asm volatile(
        "mma.sync.aligned.m16n8k16.row.col.f32.f16.f16.f32 "
        "{%0,%1,%2,%3}, {%4,%5,%6,%7}, {%8,%9}, {%0,%1,%2,%3};"
        : "+f"(c0), "+f"(c1), "+f"(c2), "+f"(c3)
        : "r"(a0), "r"(a1), "r"(a2), "r"(a3), "r"(b0), "r"(b1));
}

extern __shared__ float smem_f[];

// Grid 128 = 8 pairs x 16 slices, 1 CTA/SM. Skewed single-pass scheme:
// mma rows 0-7 = group gA step t, rows 8-15 = group gB step t-1.
// Warp w = hq*4+kq. Stage role: tile rows hq*4..+4 of k-strip kq, fp32->fp16
// RN conversion inline. Poll role: lanes 0-15 poll the 16 (slice,row) flags
// this warp's stage needs, in parallel. Reduce role: warp w owns mma row w;
// publishes its own row flag (syncwarp + lane0 release).
__global__ void __launch_bounds__(THREADS, 1)
flipflop_main(const float* __restrict__ inputs,
              const float* __restrict__ Wv,
              const float* __restrict__ Pv,
              const float* __restrict__ bv,
              const float* __restrict__ Wz,
              const float* __restrict__ Pz,
              const float* __restrict__ bz,
              const float* __restrict__ fcW,
              const float* __restrict__ fcb,
              float* __restrict__ out,
              float* __restrict__ hidden)
{
    u32*   rW = (u32*)smem_f;                 // [16][RSTRIDE] f16x2 words, 16.6 KB
    float* ps = smem_f + 16 * RSTRIDE;        // 2 x [4kq][2][16rows][PSTRIDE]

    const int tid   = threadIdx.x;
    const int pair  = blockIdx.x >> 4;
    const int slice = blockIdx.x & 15;
    const int gA    = pair * 2, gB = gA + 1;
    const int gbA   = gA * BGr, gbB = gB * BGr;
    const int w     = tid >> 5;
    const int lane  = tid & 31;
    const int hq    = w >> 2;
    const int kq    = w & 3;
    const int g     = lane >> 2;
    const int t4    = lane & 3;
    const int hh    = lane;
    const int hg    = slice * HS + hh;

    // ---- B fragments (weights) in registers, fp16 RN, 32 regs ----
    // block kb covers k = kq*128 + kb*16 .. +16.
    // b0 = {B[2t4], B[2t4+1]} (col g), b1 = {B[2t4+8], B[2t4+9]}.
    u32 bz0[8], bz1[8], bv0[8], bv1[8];
    {
        const int hB = slice * HS + hq * 8 + g;
        const float* zrow = Wz + (size_t)hB * NH + kq * 128 + 2 * t4;
        const float* vrow = Wv + (size_t)hB * NH + kq * 128 + 2 * t4;
        #pragma unroll
        for (int kb = 0; kb < 8; ++kb) {
            bz0[kb] = pack_h2(zrow[kb*16],     zrow[kb*16 + 1]);
            bz1[kb] = pack_h2(zrow[kb*16 + 8], zrow[kb*16 + 9]);
            bv0[kb] = pack_h2(vrow[kb*16],     vrow[kb*16 + 1]);
            bv1[kb] = pack_h2(vrow[kb*16 + 8], vrow[kb*16 + 9]);
        }
    }

    // parity probes (slots at t=NT-1 are rewritten only at launch end; group
    // CTAs are dataflow-coupled within +-1 iteration -> race-free at start)
    int parA, parB;
    asm volatile("ld.relaxed.gpu.global.s32 %0, [%1];"
                 : "=r"(parA) : "l"(&g_flag[gA][slice][0][NT-1]));
    asm volatile("ld.relaxed.gpu.global.s32 %0, [%1];"
                 : "=r"(parB) : "l"(&g_flag[gB][slice][0][NT-1]));
    const int readyA = parA ^ 1, readyB = parB ^ 1;

    // ---- reduce-role constants ----
    const float pz0 = Pz[hg*3+0], pz1 = Pz[hg*3+1], pz2 = Pz[hg*3+2];
    float pm0 = 0.f, pm1 = 0.f, pm2 = 0.f;        // P_m: bottom half zeroed
    if (hg < NH/2) { pm0 = Pv[hg*3+0]; pm1 = Pv[hg*3+1]; pm2 = Pv[hg*3+2]; }
    const float bzr = bz[hg];
    const float bvr = bv[hg];
    const int   rrow  = w & 7;
    const int   myrow = (w < 8) ? (gbA + rrow) : (gbB + rrow);
    const float* xrow = inputs + (size_t)myrow * NT * ND;
    float*       hout = hidden + ((size_t)myrow * NT) * NH + hg;
    int* myflag = (w < 8) ? &g_flag[gA][slice][rrow][0]
                          : &g_flag[gB][slice][rrow][0];
    const int myready = (w < 8) ? readyA : readyB;

    // ---- stage-role: warp stages tile rows [hq*4, hq*4+4) of k-strip kq ----
    const bool stA    = (hq < 2);                 // tile rows 0-7 <- group A
    const int  srow   = hq * 4 + (lane >> 3);     // tile row 0..15
    const int  sch    = (lane & 7) * 4;           // float chunk within window
    const int  sgrow  = stA ? (gbA + (srow & 7)) : (gbB + (srow & 7));
    const float* sg   = hidden + ((size_t)sgrow * NT) * NH + kq * 128 + sch;
    u32*        sd    = rW + srow * RSTRIDE + kq * 64 + (lane & 7) * 2;

    // ---- poll-role: lane l<16 polls (slice kq*4 + (l&3), group-row ...) ----
    const int  ps_s   = lane & 3;                 // producer slice within quad
    const int  ps_r   = (hq & 1) * 4 + (lane >> 2); // group row (lanes < 16)
    const int* pollp  = stA ? &g_flag[gA][kq*4 + ps_s][ps_r & 7][0]
                            : &g_flag[gB][kq*4 + ps_s][ps_r & 7][0];
    const int  pollpar = stA ? parA : parB;

    // ---- A-frag / psum indices (word offsets) ----
    const int ab0 = g * RSTRIDE + t4;
    const int ab1 = (g + 8) * RSTRIDE + t4;
    const int koff0 = kq * 64;                    // strip base in words
    const int psz_i = ((kq * 2 + 0) * 16 + g) * PSTRIDE + hq * 8 + t4 * 2;
    const int psv_i = ((kq * 2 + 1) * 16 + g) * PSTRIDE + hq * 8 + t4 * 2;

    // zero rW -> r0 = 0 for both groups (fp16 zero = 0x0000)
    for (int i = tid; i < 16 * RSTRIDE; i += THREADS) rW[i] = 0u;
    __syncthreads();

    float r_prev = 0.f;          // w<8: r_A(t-1)[row]; w>=8: r_B(t-2)[row]

    for (int t = 0; t <= NT; ++t) {
        // prefetch this warp's x (A: step t; B: step t-1)
        float x0 = 0.f, x1 = 0.f, x2 = 0.f;
        {
            const int xs = (w < 8) ? t : (t - 1);
            if (xs >= 0 && xs < NT) {
                x0 = xrow[xs*3+0]; x1 = xrow[xs*3+1]; x2 = xrow[xs*3+2];
            }
        }

        const bool do_stage = stA ? (t >= 1 && t < NT) : (t >= 2);
        const int  tsrc     = stA ? (t - 1) : (t - 2);

        // ---- poll: 16 lanes in parallel, one (slice,row) flag each ----
        if (do_stage && lane < 16)
            wait_flag(pollp + tsrc, pollpar);
        __syncwarp();

        // ---- stage: fp32 -> fp16 RN, STS.64 per 32k window ----
        if (do_stage) {
            const float* s = sg + (size_t)tsrc * NH;
            #pragma unroll
            for (int j = 0; j < 4; ++j) {                 // windows of 32 k
                const float4 v = *(const float4*)(s + j * 32);
                uint2 o;
                o.x = pack_h2(v.x, v.y);
                o.y = pack_h2(v.z, v.w);
                *(uint2*)(sd + j * 16) = o;
            }
        }
        asm volatile("bar.sync %0, 128;" :: "r"(1 + kq) : "memory");

        // ---- single mma pass: rows 0-7 = A(t), rows 8-15 = B(t-1) ----
        float* pb = ps + (t & 1) * PSUMW;
        if (t >= 1) {
            float cz0=0.f,cz1=0.f,cz2=0.f,cz3=0.f, cv0=0.f,cv1=0.f,cv2=0.f,cv3=0.f;
            #pragma unroll
            for (int kb = 0; kb < 8; ++kb) {
                const int ko = koff0 + kb * 8;
                u32 a0 = rW[ab0 + ko],     a1 = rW[ab1 + ko];
                u32 a2 = rW[ab0 + ko + 4], a3 = rW[ab1 + ko + 4];
                mma_f16(cz0,cz1,cz2,cz3, a0,a1,a2,a3, bz0[kb],bz1[kb]);
                mma_f16(cv0,cv1,cv2,cv3, a0,a1,a2,a3, bv0[kb],bv1[kb]);
            }
            *(float2*)(pb + psz_i)               = make_float2(cz0, cz1);
            *(float2*)(pb + psz_i + 8 * PSTRIDE) = make_float2(cz2, cz3);
            *(float2*)(pb + psv_i)               = make_float2(cv0, cv1);
            *(float2*)(pb + psv_i + 8 * PSTRIDE) = make_float2(cv2, cv3);
        }
        __syncthreads();                          // psum complete (only CTA sync)

        // ---- reduce + gates + per-warp publish: warp w owns mma row w ----
        {
            const int xs   = (w < 8) ? t : (t - 1);      // step this warp emits
            const bool run = (xs >= 0) && (xs < NT);
            const bool hasp = (w < 8) ? (t >= 1) : (t >= 2);
            if (run) {
                float sz = 0.f, sv = 0.f;
                if (hasp) {
                    #pragma unroll
                    for (int q = 0; q < 4; ++q) {
                        sz += pb[((q*2 + 0) * 16 + w) * PSTRIDE + hh];
                        sv += pb[((q*2 + 1) * 16 + w) * PSTRIDE + hh];
                    }
                }
                const float az = sz + x0*pz0 + x1*pz1 + x2*pz2 + bzr;
                const float av = sv + x0*pm0 + x1*pm1 + x2*pm2 + bvr;
                const float z  = 1.f / (1.f + __expf(-az));
                const float c  = 1.f / (1.f + __expf(-av));
                const float rn = fmaf(z, c - r_prev, r_prev);
                r_prev = rn;
                hout[(size_t)xs * NH] = rn;
                __syncwarp();                     // order lane STGs before release
                if (hh == 0)
                    asm volatile("st.release.gpu.global.s32 [%0], %1;"
                                 :: "l"(myflag + xs), "r"(myready) : "memory");
            }
        }
    }

    // wait for every (group,row) final flag of this slice pair before fc
    if (lane < 8)       wait_flag(&g_flag[gA][w][lane][NT-1], parA);
    else if (lane < 16) wait_flag(&g_flag[gB][w][lane-8][NT-1], parB);
    __syncthreads();

    // ================= fc epilogue =================
    float* fw = smem_f;                           // reuse smem
    for (int i = tid; i < NC * NH; i += THREADS) fw[i] = fcW[i];
    const float fb0 = fcb[0], fb1 = fcb[1], fb2 = fcb[2];
    __syncthreads();

    float4 fw0[4], fw1[4], fw2[4];
    #pragma unroll
    for (int j = 0; j < 4; ++j) {
        const int i = hh + j * 32;
        fw0[j] = ((const float4*)(fw + 0 * NH))[i];
        fw1[j] = ((const float4*)(fw + 1 * NH))[i];
        fw2[j] = ((const float4*)(fw + 2 * NH))[i];
    }

    const int row = myrow;
    const int t0  = slice * (NT / NSLICE);
    const float* hp = hidden + ((size_t)row * NT + t0) * NH;
    float*       op = out    + ((size_t)row * NT + t0) * NC;

    for (int it = 0; it < NT / NSLICE; ++it) {
        const float4* h4 = (const float4*)(hp + (size_t)it * NH);
        float a0 = 0.f, a1 = 0.f, a2 = 0.f;
        #pragma unroll
        for (int j = 0; j < 4; ++j) {
            float4 h = h4[hh + j * 32];
            a0 += h.x*fw0[j].x + h.y*fw0[j].y + h.z*fw0[j].z + h.w*fw0[j].w;
            a1 += h.x*fw1[j].x + h.y*fw1[j].y + h.z*fw1[j].z + h.w*fw1[j].w;
            a2 += h.x*fw2[j].x + h.y*fw2[j].y + h.z*fw2[j].z + h.w*fw2[j].w;
        }
        #pragma unroll
        for (int o = 16; o; o >>= 1) {
            a0 += __shfl_down_sync(0xffffffffu, a0, o);
            a1 += __shfl_down_sync(0xffffffffu, a1, o);
            a2 += __shfl_down_sync(0xffffffffu, a2, o);
        }
        if (hh == 0) {
            op[it*3+0] = a0 + fb0;
            op[it*3+1] = a1 + fb1;
            op[it*3+2] = a2 + fb2;
        }
    }
}

extern "C" void kernel_launch(void* const* d_in, const int* in_sizes, int n_in,
                              void* d_out, int out_size)
{
    const float* inputs = (const float*)d_in[0];
    const float* Wv     = (const float*)d_in[1];
    const float* Pv     = (const float*)d_in[2];
    const float* b_v    = (const float*)d_in[3];
    const float* Wz     = (const float*)d_in[4];
    const float* Pz     = (const float*)d_in[5];
    const float* b_z    = (const float*)d_in[6];
    const float* fcW    = (const float*)d_in[7];
    const float* fcb    = (const float*)d_in[8];

    // outputs concatenated in reference return order: out (B,T,C) then hidden (B,T,H)
    float* out    = (float*)d_out;
    float* hidden = out + (size_t)NB * NT * NC;

    const int smem_bytes = (16 * RSTRIDE + 2 * PSUMW) * 4;
    cudaFuncSetAttribute(flipflop_main,
                         cudaFuncAttributeMaxDynamicSharedMemorySize, smem_bytes);

    flipflop_main<<<(NGRP / 2) * NSLICE, THREADS, smem_bytes>>>(
        inputs, Wv, Pv, b_v, Wz, Pz, b_z, fcW, fcb, out, hidden);
}